// round 8
// baseline (speedup 1.0000x reference)
#include <cuda_runtime.h>
#include <math.h>

// Problem constants (fixed shapes per reference)
#define B_DIM 16
#define K_DIM 64
#define H_DIM 96
#define W_DIM 96
#define HW    (H_DIM * W_DIM)            // 9216
#define MAPS  (B_DIM * K_DIM)            // 1024
#define NMAPS_TOTAL (2 * MAPS)           // 2048 (both stacks)
#define DK_ELEMS ((size_t)MAPS * HW)     // 9,437,184 per stack
#define KP_ELEMS ((size_t)B_DIM * 3 * K_DIM * 2)  // 6144 per stack
#define Z_ELEMS  ((size_t)B_DIM * K_DIM)          // 1024 per stack

#define NTHREADS 384                     // 12 warps; 2304 float4 = 384 * 6
#define NWARPS   12
#define NIT      6

// Per-warp partial sums: [component(z,x,y)][warp][map] for coalesced kernel-2 reads.
__device__ float g_partials[3][NWARPS][NMAPS_TOTAL];

// ---------------------------------------------------------------------------
// Kernel 1: streaming sigmoid + per-warp partial reductions.
//  - input loads DEFAULT policy: 75.5MB input fits L2 and is re-read every
//    graph replay -> steady-state L2 hits.
//  - output stores __stcs (evict-first): write-only stream, don't pollute L2.
//  - NO __syncthreads, NO serial tail: lane 0 of each warp writes 3 floats
//    and the warp retires. Decode happens in kernel 2.
// ---------------------------------------------------------------------------
__global__ __launch_bounds__(NTHREADS, 4)
void dcm2kp_stream(const float* __restrict__ Rk,
                   const float* __restrict__ tfRk,
                   float* __restrict__ out)
{
    const int bid = blockIdx.x;          // [0, 2048)
    const int s   = bid >> 10;           // stack: 0 = Rk, 1 = tf_Rk
    const int bk  = bid & 1023;          // map index within stack

    const float* __restrict__ in = (s ? tfRk : Rk) + (size_t)bk * HW;
    float* __restrict__ dkout = out + (size_t)s * DK_ELEMS + (size_t)bk * HW;

    const int t = threadIdx.x;

    const float4* __restrict__ in4 = reinterpret_cast<const float4*>(in);
    float4* __restrict__ out4 = reinterpret_cast<float4*>(dkout);

    // ---- Phase 1: batch ALL loads up front (MLP = 6 per thread) ----
    float4 v[NIT];
    #pragma unroll
    for (int it = 0; it < NIT; ++it) {
        v[it] = in4[t + it * NTHREADS];      // default: L2-resident across replays
    }

    // ---- Phase 2: sigmoid -> evict-first store -> accumulate ----
    float zs = 0.0f, kxs = 0.0f, kys = 0.0f;

    #pragma unroll
    for (int it = 0; it < NIT; ++it) {
        const int j = t + it * NTHREADS;     // float4 index, [0, 2304)
        const int e = j << 2;                // element index, [0, 9216)

        // fast sigmoid (MUFU EX2 + RCP); rel err ~5e-7, fine for 1e-3 tol
        const float d0 = 1.0f / (1.0f + __expf(-v[it].x));
        const float d1 = 1.0f / (1.0f + __expf(-v[it].y));
        const float d2 = 1.0f / (1.0f + __expf(-v[it].z));
        const float d3 = 1.0f / (1.0f + __expf(-v[it].w));

        __stcs(&out4[j], make_float4(d0, d1, d2, d3));  // write-only stream

        // 4 consecutive elements share the row (96 % 4 == 0, e % 4 == 0)
        const int h  = e / 96;
        const int w0 = e - h * 96;

        const float s4 = (d0 + d1) + (d2 + d3);
        zs  += s4;
        kxs += fmaf((float)w0, s4, d1 + 2.0f * d2 + 3.0f * d3);
        kys += (float)h * s4;
    }

    // ---- Phase 3: warp reduction, lane 0 writes partials, warp retires ----
    #pragma unroll
    for (int o = 16; o > 0; o >>= 1) {
        zs  += __shfl_down_sync(0xffffffffu, zs,  o);
        kxs += __shfl_down_sync(0xffffffffu, kxs, o);
        kys += __shfl_down_sync(0xffffffffu, kys, o);
    }

    const int wid = t >> 5;
    if ((t & 31) == 0) {
        g_partials[0][wid][bid] = zs;
        g_partials[1][wid][bid] = kxs;
        g_partials[2][wid][bid] = kys;
    }
}

// ---------------------------------------------------------------------------
// Kernel 2: decode. One thread per map (2048 threads). Sums the 12 per-warp
// partials in double, soft-argmax round, gathers the sigmoid value (input is
// L2-resident now), writes 6 keypoint floats + zeta.
// ---------------------------------------------------------------------------
__global__ __launch_bounds__(256)
void dcm2kp_decode(const float* __restrict__ Rk,
                   const float* __restrict__ tfRk,
                   float* __restrict__ out)
{
    const int m = blockIdx.x * 256 + threadIdx.x;   // [0, 2048)
    if (m >= NMAPS_TOTAL) return;

    const int s  = m >> 10;
    const int bk = m & 1023;

    double z = 0.0, x = 0.0, y = 0.0;
    #pragma unroll
    for (int w = 0; w < NWARPS; ++w) {
        z += (double)g_partials[0][w][m];
        x += (double)g_partials[1][w][m];
        y += (double)g_partials[2][w][m];
    }

    // jnp.round == round-half-to-even == rintf (default rounding mode)
    const float xr = rintf((float)(x / z));
    const float yr = rintf((float)(y / z));

    int wi = (int)xr; wi = wi < 0 ? 0 : (wi > 95 ? 95 : wi);
    int hi = (int)yr; hi = hi < 0 ? 0 : (hi > 95 ? 95 : hi);

    const float* __restrict__ in = (s ? tfRk : Rk) + (size_t)bk * HW;
    // gathered d: precise sigmoid (trunc boundaries are sensitive)
    const float dg = 1.0f / (1.0f + expf(-in[hi * 96 + wi]));

    const int b = bk >> 6;   // bk / 64
    const int k = bk & 63;   // bk % 64

    float* __restrict__ kpbase = out + 2 * DK_ELEMS + (size_t)s * KP_ELEMS
                               + (size_t)b * (3 * K_DIM * 2);
    float* __restrict__ zbase  = out + 2 * DK_ELEMS + 2 * KP_ELEMS
                               + (size_t)s * Z_ELEMS;

    // kp
    kpbase[k * 2 + 0] = xr;
    kpbase[k * 2 + 1] = yr;
    // kp1 = trunc(kp + kp*d)
    kpbase[(K_DIM + k) * 2 + 0] = truncf(xr + xr * dg);
    kpbase[(K_DIM + k) * 2 + 1] = truncf(yr + yr * dg);
    // kp2 = trunc(kp - kp*d)
    kpbase[(2 * K_DIM + k) * 2 + 0] = truncf(xr - xr * dg);
    kpbase[(2 * K_DIM + k) * 2 + 1] = truncf(yr - yr * dg);

    zbase[b * K_DIM + k] = (float)z;
}

extern "C" void kernel_launch(void* const* d_in, const int* in_sizes, int n_in,
                              void* d_out, int out_size)
{
    (void)in_sizes; (void)n_in; (void)out_size;
    const float* Rk   = (const float*)d_in[0];
    const float* tfRk = (const float*)d_in[1];
    float* out = (float*)d_out;

    dcm2kp_stream<<<NMAPS_TOTAL, NTHREADS>>>(Rk, tfRk, out);
    dcm2kp_decode<<<NMAPS_TOTAL / 256, 256>>>(Rk, tfRk, out);
}